// round 5
// baseline (speedup 1.0000x reference)
#include <cuda_runtime.h>
#include <cuda_bf16.h>
#include <math.h>
#include <stdint.h>

#define TT 64
#define DIMM 2048
#define SLOTSS 256
#define KS 16
#define KPER (DIMM / KS)    // 128
#define NCHUNK (KPER / 16)  // 8
#define SPAD 40
#define NB 256

// -------- device scratch --------
__device__ float g_h[TT * DIMM];
__device__ float g_x[TT * DIMM];
__device__ float g_lv[TT * DIMM];
__device__ float g_gated[TT * DIMM];
__device__ float g_er[TT * DIMM];
__device__ float g_ad[TT * DIMM];
__device__ float g_pA[KS * TT * DIMM];
__device__ float g_pB[KS * TT * DIMM];
__device__ float g_pS[KS * TT * SLOTSS];
__device__ float g_lg[TT * SLOTSS];
__device__ float g_c[TT * SLOTSS];
__device__ unsigned g_count = 0;
__device__ unsigned g_gen = 0;

__device__ __forceinline__ float sigmoidf_(float v) { return 1.f / (1.f + expf(-v)); }

enum { M_RELU = 0, M_ID, M_LIG, M_GATE };

// -------- shared memory union across phases --------
struct SmemG { __nv_bfloat16 As[2][64][SPAD]; __nv_bfloat16 Ws[2][128][SPAD]; };
struct SmemM { float cs[64][32]; float es[64][64]; float ds[64][64]; };
struct SmemS { float rowmax[64]; };
union SmemU { SmemG g; SmemM m; SmemS s; };

// -------- software grid barrier (all NB blocks resident) --------
__device__ __forceinline__ void gridbar() {
    __threadfence();
    __syncthreads();
    if (threadIdx.x == 0) {
        unsigned gen = *(volatile unsigned*)&g_gen;
        unsigned prev = atomicAdd(&g_count, 1);
        if (prev == NB - 1) {
            g_count = 0;
            __threadfence();
            *(volatile unsigned*)&g_gen = gen + 1;
        } else {
            while (*(volatile unsigned*)&g_gen == gen) { __nanosleep(32); }
        }
        __threadfence();
    }
    __syncthreads();
}

// -------- tensor-core GEMM phase --------
__device__ __forceinline__ void ldsm4(uint32_t* r, uint32_t addr) {
    asm volatile("ldmatrix.sync.aligned.m8n8.x4.shared.b16 {%0,%1,%2,%3}, [%4];"
                 : "=r"(r[0]), "=r"(r[1]), "=r"(r[2]), "=r"(r[3]) : "r"(addr));
}
__device__ __forceinline__ void mma16816(float* d, const uint32_t* a, uint32_t b0, uint32_t b1) {
    asm volatile(
        "mma.sync.aligned.m16n8k16.row.col.f32.bf16.bf16.f32 "
        "{%0,%1,%2,%3}, {%4,%5,%6,%7}, {%8,%9}, {%0,%1,%2,%3};"
        : "+f"(d[0]), "+f"(d[1]), "+f"(d[2]), "+f"(d[3])
        : "r"(a[0]), "r"(a[1]), "r"(a[2]), "r"(a[3]), "r"(b0), "r"(b1));
}

template <int PREP, int ACG>
__device__ void gemm_phase(SmemU* sm, const float* __restrict__ A,
                           const float* __restrict__ W, float* __restrict__ part,
                           int Ntot, int nblk,
                           const float* __restrict__ noise, const int* __restrict__ idx) {
    const int bid = blockIdx.x;
    const int tid = threadIdx.x;
    const int n0 = (bid % nblk) * 128;
    const int kb = (bid / nblk) * KPER;

    const int a_row = tid >> 2, a_kq = (tid & 3) * 4;
    const float* Ag;
    const float* Ng = nullptr;
    if (PREP) {
        int row = __ldg(&idx[a_row]);
        Ag = A + (size_t)row * DIMM + kb + a_kq;
        Ng = noise + (size_t)a_row * DIMM + kb + a_kq;
    } else {
        Ag = A + (size_t)a_row * DIMM + kb + a_kq;
    }
    const int w_row = tid >> 1, w_kq = (tid & 1) * 8;
    const float* Wgp = W + (size_t)(n0 + w_row) * DIMM + kb + w_kq;

    const int lane = tid & 31, wid = tid >> 5;
    const int m0w = (wid >> 2) * 32;
    const int n0w = (wid & 3) * 32;
    const int gq = lane >> 3, rq = lane & 7;
    const int aoff = (m0w + (gq & 1) * 8 + rq) * SPAD + (gq >> 1) * 8;
    const int boff = (n0w + (gq >> 1) * 8 + rq) * SPAD + (gq & 1) * 8;

    const uint32_t asbase = (uint32_t)__cvta_generic_to_shared(&sm->g.As[0][0][0]);
    const uint32_t wsbase = (uint32_t)__cvta_generic_to_shared(&sm->g.Ws[0][0][0]);
    const uint32_t ABUF = 64 * SPAD * 2, WBUF = 128 * SPAD * 2;

    float avs[3][4], wvs[3][8];

#define LOAD_CHUNK(st, c)                                                    \
    {                                                                        \
        float4 t4 = ACG ? __ldcg((const float4*)(Ag + (c) * 16))             \
                        : __ldg((const float4*)(Ag + (c) * 16));             \
        if (PREP) {                                                          \
            float4 n4 = __ldg((const float4*)(Ng + (c) * 16));               \
            t4.x = fmaf(0.01f, n4.x, t4.x); t4.y = fmaf(0.01f, n4.y, t4.y);  \
            t4.z = fmaf(0.01f, n4.z, t4.z); t4.w = fmaf(0.01f, n4.w, t4.w);  \
        }                                                                    \
        avs[st][0] = t4.x; avs[st][1] = t4.y;                                \
        avs[st][2] = t4.z; avs[st][3] = t4.w;                                \
        float4 u0 = __ldg((const float4*)(Wgp + (c) * 16));                  \
        float4 u1 = __ldg((const float4*)(Wgp + (c) * 16 + 4));              \
        wvs[st][0] = u0.x; wvs[st][1] = u0.y; wvs[st][2] = u0.z;             \
        wvs[st][3] = u0.w; wvs[st][4] = u1.x; wvs[st][5] = u1.y;             \
        wvs[st][6] = u1.z; wvs[st][7] = u1.w;                                \
    }
#define CVT_STORE(st, buf)                                                   \
    {                                                                        \
        _Pragma("unroll") for (int i = 0; i < 4; i++) {                      \
            __nv_bfloat16 hi = __float2bfloat16(avs[st][i]);                 \
            float rem = avs[st][i] - __bfloat162float(hi);                   \
            sm->g.As[buf][a_row][a_kq + i] = hi;                             \
            sm->g.As[buf][a_row][a_kq + i + 16] = __float2bfloat16(rem);     \
        }                                                                    \
        _Pragma("unroll") for (int i = 0; i < 8; i++) {                      \
            __nv_bfloat16 hi = __float2bfloat16(wvs[st][i]);                 \
            float rem = wvs[st][i] - __bfloat162float(hi);                   \
            sm->g.Ws[buf][w_row][w_kq + i] = hi;                             \
            sm->g.Ws[buf][w_row][w_kq + i + 16] = __float2bfloat16(rem);     \
        }                                                                    \
    }

    LOAD_CHUNK(0, 0);
    LOAD_CHUNK(1, 1);
    LOAD_CHUNK(2, 2);
    CVT_STORE(0, 0);
    __syncthreads();

    float d[2][4][4];
#pragma unroll
    for (int mt = 0; mt < 2; mt++)
#pragma unroll
        for (int nf = 0; nf < 4; nf++)
#pragma unroll
            for (int j = 0; j < 4; j++) d[mt][nf][j] = 0.f;

#pragma unroll
    for (int c = 0; c < NCHUNK; c++) {
        const int cur = c & 1;
        if (c + 3 < NCHUNK) LOAD_CHUNK(c % 3, c + 3);

        uint32_t a[2][2][4], b[2][2][4];
#pragma unroll
        for (int mt = 0; mt < 2; mt++)
#pragma unroll
            for (int sec = 0; sec < 2; sec++)
                ldsm4(a[mt][sec], asbase + cur * ABUF + (uint32_t)(aoff + mt * 16 * SPAD + sec * 16) * 2);
#pragma unroll
        for (int pr = 0; pr < 2; pr++)
#pragma unroll
            for (int sec = 0; sec < 2; sec++)
                ldsm4(b[pr][sec], wsbase + cur * WBUF + (uint32_t)(boff + pr * 16 * SPAD + sec * 16) * 2);
#pragma unroll
        for (int q = 0; q < 3; q++) {
            const int as = (q == 2) ? 1 : 0;
            const int ws = (q == 1) ? 1 : 0;
#pragma unroll
            for (int mt = 0; mt < 2; mt++)
#pragma unroll
                for (int nf = 0; nf < 4; nf++) {
                    const int pr = nf >> 1, hl = nf & 1;
                    mma16816(d[mt][nf], a[mt][as], b[pr][ws][hl * 2], b[pr][ws][hl * 2 + 1]);
                }
        }
        if (c + 1 < NCHUNK) CVT_STORE((c + 1) % 3, cur ^ 1);
        __syncthreads();
    }
#undef LOAD_CHUNK
#undef CVT_STORE

    const int mbase = (bid / nblk) * 64;
#pragma unroll
    for (int mt = 0; mt < 2; mt++)
#pragma unroll
        for (int nf = 0; nf < 4; nf++) {
            const int m = m0w + mt * 16 + (lane >> 2);
            const int n = n0 + n0w + nf * 8 + (lane & 3) * 2;
            *(float2*)&part[(size_t)(mbase + m) * Ntot + n] = make_float2(d[mt][nf][0], d[mt][nf][1]);
            *(float2*)&part[(size_t)(mbase + m + 8) * Ntot + n] = make_float2(d[mt][nf][2], d[mt][nf][3]);
        }
}

// -------- reduce + activation: pair-split k across adjacent threads ---------
template <int MODE>
__device__ void reduce_phase(const float* __restrict__ part, const float* __restrict__ bias,
                             float* __restrict__ out, const float* __restrict__ xbuf,
                             const float* __restrict__ vw, const float* __restrict__ vb) {
    const int gid = blockIdx.x * 256 + threadIdx.x;  // 0..65535
    const int flat = (gid >> 1) * 4;                 // f4 index shared by the pair
    const int kh = (gid & 1) * 8;
    float acc[4] = {0.f, 0.f, 0.f, 0.f};
#pragma unroll
    for (int k = 0; k < 8; k++) {
        float4 p = __ldcg((const float4*)&part[(size_t)(kh + k) * TT * DIMM + flat]);
        acc[0] += p.x; acc[1] += p.y; acc[2] += p.z; acc[3] += p.w;
    }
#pragma unroll
    for (int j = 0; j < 4; j++) acc[j] += __shfl_xor_sync(0xffffffffu, acc[j], 1);
    if (gid & 1) return;
    const int t = flat / DIMM;
    const int n = flat % DIMM;
    float4 b4 = __ldg((const float4*)&bias[n]);
    float bb[4] = {b4.x, b4.y, b4.z, b4.w};
    float res[4];
    float4 xv;
    if (MODE == M_GATE) xv = __ldcg((const float4*)&xbuf[flat]);
    const float* xp = (const float*)&xv;
#pragma unroll
    for (int j = 0; j < 4; j++) {
        const float v = acc[j] + bb[j];
        if (MODE == M_RELU) {
            res[j] = v > 0.f ? v : 0.f;
        } else if (MODE == M_ID) {
            res[j] = v;
        } else if (MODE == M_LIG) {
            float ang = fmodf(0.37699111843077515f * (float)(t + 1), 6.2831853071795865f);
            float ps = -cosf(ang);
            float volt = sigmoidf_(fmaf(ps, __ldg(&vw[n + j]), __ldg(&vb[n + j])));
            res[j] = sigmoidf_(v) * volt;
        } else {  // M_GATE
            res[j] = xp[j] * sigmoidf_(v);
        }
    }
    *(float4*)&out[flat] = make_float4(res[0], res[1], res[2], res[3]);
}

// -------- fused tail reduce: er (lo half), ad+lg (hi half) ------------------
__device__ void tail_phase(const float* __restrict__ pA, const float* __restrict__ be,
                           const float* __restrict__ pB, const float* __restrict__ bad,
                           const float* __restrict__ pS, const float* __restrict__ ba,
                           float* __restrict__ er, float* __restrict__ ad,
                           float* __restrict__ lg) {
    const int gid = blockIdx.x * 256 + threadIdx.x;  // 0..65535
    if (gid < 32768) {
        const int flat = gid * 4;
        const int n = flat % DIMM;
        float aA[4] = {0, 0, 0, 0};
#pragma unroll
        for (int k = 0; k < KS; k++) {
            float4 p = __ldcg((const float4*)&pA[(size_t)k * TT * DIMM + flat]);
            aA[0] += p.x; aA[1] += p.y; aA[2] += p.z; aA[3] += p.w;
        }
        float4 e4 = __ldg((const float4*)&be[n]);
        const float* ep = (const float*)&e4;
        float ro[4];
#pragma unroll
        for (int j = 0; j < 4; j++) ro[j] = sigmoidf_(aA[j] + ep[j]);
        *(float4*)&er[flat] = make_float4(ro[0], ro[1], ro[2], ro[3]);
    } else {
        const int j0 = gid - 32768;
        const int flat = j0 * 4;
        const int n = flat % DIMM;
        float aB[4] = {0, 0, 0, 0};
#pragma unroll
        for (int k = 0; k < KS; k++) {
            float4 q = __ldcg((const float4*)&pB[(size_t)k * TT * DIMM + flat]);
            aB[0] += q.x; aB[1] += q.y; aB[2] += q.z; aB[3] += q.w;
        }
        float4 d4 = __ldg((const float4*)&bad[n]);
        const float* dp = (const float*)&d4;
        *(float4*)&ad[flat] = make_float4(aB[0] + dp[0], aB[1] + dp[1], aB[2] + dp[2], aB[3] + dp[3]);
        if (j0 < 4096) {
            const int fl = j0 * 4;
            const int ns = fl % SLOTSS;
            float aS[4] = {0, 0, 0, 0};
#pragma unroll
            for (int k = 0; k < KS; k++) {
                float4 p = __ldcg((const float4*)&pS[(size_t)k * TT * SLOTSS + fl]);
                aS[0] += p.x; aS[1] += p.y; aS[2] += p.z; aS[3] += p.w;
            }
            float4 b4 = __ldg((const float4*)&ba[ns]);
            *(float4*)&lg[fl] = make_float4(aS[0] + b4.x, aS[1] + b4.y, aS[2] + b4.z, aS[3] + b4.w);
        }
    }
}

// -------- softmax chain: parallel rowmax + single-warp prefetched chain -----
__device__ void softmax_phase(SmemU* sm, const float* __restrict__ lg,
                              float* __restrict__ cbuf) {
    const int tid = threadIdx.x, lane = tid & 31, wid = tid >> 5;
    __syncthreads();
    // rowmax: warp w handles rows 8w..8w+7
#pragma unroll
    for (int r = 0; r < 8; r++) {
        const int row = wid * 8 + r;
        float m = -1e30f;
#pragma unroll
        for (int j = 0; j < 8; j++) m = fmaxf(m, __ldcg(&lg[row * SLOTSS + j * 32 + lane]));
#pragma unroll
        for (int o = 16; o > 0; o >>= 1) m = fmaxf(m, __shfl_xor_sync(0xffffffffu, m, o));
        if (lane == 0) sm->s.rowmax[row] = m;
    }
    __syncthreads();
    if (wid != 0) return;

    // single-warp chain: lane holds slots lane + 32*j, distance-2 prefetch
    float u[8];
#pragma unroll
    for (int j = 0; j < 8; j++) u[j] = 0.f;
    float pre[2][8];
#pragma unroll
    for (int j = 0; j < 8; j++) {
        pre[0][j] = __ldcg(&lg[0 * SLOTSS + j * 32 + lane]) - sm->s.rowmax[0];
        pre[1][j] = __ldcg(&lg[1 * SLOTSS + j * 32 + lane]) - sm->s.rowmax[1];
    }
    for (int t = 0; t < TT; t++) {
        float cur[8];
#pragma unroll
        for (int j = 0; j < 8; j++) cur[j] = pre[t & 1][j];
        if (t + 2 < TT) {
            const float rm = sm->s.rowmax[t + 2];
#pragma unroll
            for (int j = 0; j < 8; j++)
                pre[t & 1][j] = __ldcg(&lg[(t + 2) * SLOTSS + j * 32 + lane]) - rm;
        }
        float f[8];
#pragma unroll
        for (int j = 0; j < 8; j++) f[j] = __expf(fmaf(-0.1f, u[j], cur[j]));
        float s01 = f[0] + f[1], s23 = f[2] + f[3], s45 = f[4] + f[5], s67 = f[6] + f[7];
        float s03 = s01 + s23, s47 = s45 + s67;
        float su = s03 + s47;
#pragma unroll
        for (int o = 16; o > 0; o >>= 1) su += __shfl_xor_sync(0xffffffffu, su, o);
        const float r = __fdividef(1.f, su);
#pragma unroll
        for (int j = 0; j < 8; j++) {
            const float w = f[j] * r;
            u[j] += w;
            cbuf[t * SLOTSS + j * 32 + lane] = 0.5f * w;
        }
    }
}

// -------- memupd: preload (overlapped with softmax) + compute ----------------
__device__ void memupd_preload(SmemU* sm, const float* __restrict__ er,
                               const float* __restrict__ ad, int tile) {
    const int tid = threadIdx.x;
    const int D0 = (tile >> 3) * 64;
#pragma unroll
    for (int j = 0; j < 4; j++) {
        int f = tid + j * 256;
        int t = f >> 4, q = (f & 15) * 4;
        *(float4*)&sm->m.es[t][q] = __ldcg((const float4*)&er[(size_t)t * DIMM + D0 + q]);
        *(float4*)&sm->m.ds[t][q] = __ldcg((const float4*)&ad[(size_t)t * DIMM + D0 + q]);
    }
}

__device__ void memupd_compute(SmemU* sm, const float* __restrict__ cbuf,
                               const float* __restrict__ mem0, float* __restrict__ out,
                               int tile) {
    const int tid = threadIdx.x;
    const int S0 = (tile & 7) * 32;
    const int D0 = (tile >> 3) * 64;
#pragma unroll
    for (int j = 0; j < 2; j++) {
        int f = tid + j * 256;
        int t = f >> 3, q = (f & 7) * 4;
        *(float4*)&sm->m.cs[t][q] = __ldcg((const float4*)&cbuf[(size_t)t * SLOTSS + S0 + q]);
    }
    __syncthreads();
    const int sg = (tid >> 4) * 2, dg = (tid & 15) * 4;
    float m[2][4];
#pragma unroll
    for (int j = 0; j < 2; j++)
        *(float4*)m[j] = __ldg((const float4*)&mem0[(size_t)(S0 + sg + j) * DIMM + D0 + dg]);
    for (int t = 0; t < 64; t++) {
        float c0 = sm->m.cs[t][sg], c1 = sm->m.cs[t][sg + 1];
        float4 e4 = *(const float4*)&sm->m.es[t][dg];
        float4 a4 = *(const float4*)&sm->m.ds[t][dg];
        float e[4] = {e4.x, e4.y, e4.z, e4.w};
        float a[4] = {a4.x, a4.y, a4.z, a4.w};
#pragma unroll
        for (int l = 0; l < 4; l++) {
            m[0][l] = fmaf(c0, fmaf(-e[l], m[0][l], a[l]), m[0][l]);
            m[1][l] = fmaf(c1, fmaf(-e[l], m[1][l], a[l]), m[1][l]);
        }
    }
#pragma unroll
    for (int j = 0; j < 2; j++)
        *(float4*)&out[(size_t)(S0 + sg + j) * DIMM + D0 + dg] = *(float4*)m[j];
}

// -------- mega kernel --------------------------------------------------------
__global__ __launch_bounds__(256, 2) void mega_kernel(
    const float* __restrict__ traces, const float* __restrict__ noise,
    const float* __restrict__ mem0,
    const float* __restrict__ W1, const float* __restrict__ b1,
    const float* __restrict__ W2, const float* __restrict__ b2,
    const float* __restrict__ Wl, const float* __restrict__ bl,
    const float* __restrict__ vw, const float* __restrict__ vb,
    const float* __restrict__ Wg, const float* __restrict__ bg,
    const float* __restrict__ Wa, const float* __restrict__ ba,
    const float* __restrict__ We, const float* __restrict__ be,
    const float* __restrict__ Wad, const float* __restrict__ bad,
    const int* __restrict__ idx, float* __restrict__ out) {
    __shared__ SmemU sm;

    gemm_phase<1, 0>(&sm, traces, W1, g_pA, DIMM, 16, noise, idx);
    gridbar();
    reduce_phase<M_RELU>(g_pA, b1, g_h, nullptr, nullptr, nullptr);
    gridbar();

    gemm_phase<0, 1>(&sm, g_h, W2, g_pA, DIMM, 16, nullptr, nullptr);
    gridbar();
    reduce_phase<M_ID>(g_pA, b2, g_x, nullptr, nullptr, nullptr);
    gridbar();

    gemm_phase<0, 1>(&sm, g_x, Wl, g_pA, DIMM, 16, nullptr, nullptr);
    gridbar();
    reduce_phase<M_LIG>(g_pA, bl, g_lv, nullptr, vw, vb);
    gridbar();

    gemm_phase<0, 1>(&sm, g_lv, Wg, g_pA, DIMM, 16, nullptr, nullptr);
    gridbar();
    reduce_phase<M_GATE>(g_pA, bg, g_gated, g_x, nullptr, nullptr);
    gridbar();

    // tri-GEMM phase: We, Wad (all blocks) + Wa (blocks 0..31)
    gemm_phase<0, 1>(&sm, g_gated, We, g_pA, DIMM, 16, nullptr, nullptr);
    __syncthreads();
    gemm_phase<0, 1>(&sm, g_gated, Wad, g_pB, DIMM, 16, nullptr, nullptr);
    if (blockIdx.x < 32) {
        __syncthreads();
        gemm_phase<0, 1>(&sm, g_gated, Wa, g_pS, SLOTSS, 2, nullptr, nullptr);
    }
    gridbar();

    tail_phase(g_pA, be, g_pB, bad, g_pS, ba, g_er, g_ad, g_lg);
    gridbar();

    // softmax (block 0) overlapped with memupd tile preload (blocks 1..255)
    if (blockIdx.x == 0) {
        softmax_phase(&sm, g_lg, g_c);
    } else {
        memupd_preload(&sm, g_er, g_ad, (int)blockIdx.x - 1);
    }
    gridbar();

    if (blockIdx.x != 0) {
        memupd_compute(&sm, g_c, mem0, out, (int)blockIdx.x - 1);
        if (blockIdx.x == NB - 1) {
            __syncthreads();
            memupd_preload(&sm, g_er, g_ad, NB - 1);
            __syncthreads();
            memupd_compute(&sm, g_c, mem0, out, NB - 1);
        }
    }
}

// ---------------------------------------------------------------------------
extern "C" void kernel_launch(void* const* d_in, const int* in_sizes, int n_in,
                              void* d_out, int out_size) {
    const float* traces = (const float*)d_in[0];
    const float* noise  = (const float*)d_in[1];
    const float* mem0   = (const float*)d_in[2];
    const float* W1 = (const float*)d_in[4];
    const float* b1 = (const float*)d_in[5];
    const float* W2 = (const float*)d_in[6];
    const float* b2 = (const float*)d_in[7];
    const float* Wl = (const float*)d_in[8];
    const float* bl = (const float*)d_in[9];
    const float* vw = (const float*)d_in[10];
    const float* vb = (const float*)d_in[11];
    const float* Wg = (const float*)d_in[12];
    const float* bg = (const float*)d_in[13];
    const float* Wa = (const float*)d_in[14];
    const float* ba = (const float*)d_in[15];
    const float* We = (const float*)d_in[16];
    const float* be = (const float*)d_in[17];
    const float* Wad = (const float*)d_in[18];
    const float* bad = (const float*)d_in[19];
    const int* idx = (const int*)d_in[20];
    float* out = (float*)d_out;

    mega_kernel<<<NB, 256>>>(traces, noise, mem0, W1, b1, W2, b2, Wl, bl, vw, vb,
                             Wg, bg, Wa, ba, We, be, Wad, bad, idx, out);
}